// round 13
// baseline (speedup 1.0000x reference)
#include <cuda_runtime.h>
#include <cuda_bf16.h>
#include <cstdint>

#define VOCAB 50257
#define EMBED 128
#define BATCH 64
#define NSENT 50
#define TC 20

#define TILE_M 128
#define NBLK ((VOCAB + TILE_M - 1) / TILE_M)   // 393
#define VPAD (NBLK * TILE_M)                   // 50304 padded vocab rows

// padded row stride for conflict-free ldmatrix: 272B = 17 x 16B
#define ROWB 272

// GEMM smem layout (bytes)
#define SM_AHI 0
#define SM_ALO (SM_AHI + TILE_M * ROWB)     // 34816
#define SM_UHI (SM_ALO + TILE_M * ROWB)     // 69632
#define SM_ULO (SM_UHI + BATCH * ROWB)      // 87040
#define SM_BIAS (SM_ULO + BATCH * ROWB)     // 104448
#define SM_TOT (SM_BIAS + 512)              // 104960 -> 2 CTAs/SM

// fused kernel smem (floats)
#define FS_M 0
#define FS_C (NSENT * EMBED)
#define FS_U (FS_C + NSENT * EMBED)
#define FS_SC (FS_U + EMBED)
#define FS_OS (FS_SC + 64)
#define FS_TOTF (FS_OS + 4 * EMBED)
#define FS_TOTB (FS_TOTF * 4)               // 54016 B

// device scratch
__device__ uint32_t g_uhi[BATCH * 64];      // u hi, [b][64 x uint32(k,k+1)]
__device__ uint32_t g_ulo[BATCH * 64];
__device__ uint4 g_whi[VPAD * 16];          // W hi bf16, row-major 256B rows (12.9MB)
__device__ uint4 g_wlo[VPAD * 16];

// ---------------------------------------------------------------------------
// helpers
// ---------------------------------------------------------------------------
__device__ __forceinline__ uint32_t smem_u32(const void* p) {
    uint32_t a;
    asm("{ .reg .u64 t; cvta.to.shared.u64 t, %1; cvt.u32.u64 %0, t; }"
        : "=r"(a) : "l"(p));
    return a;
}
__device__ __forceinline__ void ldsm_x4(uint32_t& r0, uint32_t& r1,
                                        uint32_t& r2, uint32_t& r3, uint32_t a) {
    asm volatile("ldmatrix.sync.aligned.m8n8.x4.shared.b16 {%0,%1,%2,%3}, [%4];"
                 : "=r"(r0), "=r"(r1), "=r"(r2), "=r"(r3) : "r"(a));
}
__device__ __forceinline__ void mma16816(float* d, const uint32_t* a,
                                         const uint32_t* b) {
    asm volatile(
        "mma.sync.aligned.m16n8k16.row.col.f32.bf16.bf16.f32 "
        "{%0,%1,%2,%3}, {%4,%5,%6,%7}, {%8,%9}, {%0,%1,%2,%3};"
        : "+f"(d[0]), "+f"(d[1]), "+f"(d[2]), "+f"(d[3])
        : "r"(a[0]), "r"(a[1]), "r"(a[2]), "r"(a[3]), "r"(b[0]), "r"(b[1]));
}
__device__ __forceinline__ uint32_t packbf(__nv_bfloat16 lo, __nv_bfloat16 hi) {
    return ((uint32_t)__bfloat16_as_ushort(hi) << 16)
         | (uint32_t)__bfloat16_as_ushort(lo);
}
__device__ __forceinline__ void split1(float x, __nv_bfloat16& h, __nv_bfloat16& l) {
    h = __float2bfloat16_rn(x);
    l = __float2bfloat16_rn(x - __bfloat162float(h));
}
#define CPA(dst, src) \
    asm volatile("cp.async.cg.shared.global [%0], [%1], 16;" \
                 :: "r"(dst), "l"(src) : "memory")
#define CPCOMMIT() asm volatile("cp.async.commit_group;" ::: "memory")
#define CPWAIT0()  asm volatile("cp.async.wait_group 0;" ::: "memory")

// ---------------------------------------------------------------------------
// Kernel 0: W fp32 -> bf16 (hi, lo) split, streaming, padded + zero tail.
// Thread handles one 16B output chunk (8 bf16 = 8 fp32 in = 2 float4 loads).
// ---------------------------------------------------------------------------
__global__ void __launch_bounds__(256) wsplit_kernel(const float4* __restrict__ W4) {
    int idx = blockIdx.x * 256 + threadIdx.x;   // < VPAD*16 = 804864
    int v = idx >> 4, q = idx & 15;
    uint4 hi = make_uint4(0u, 0u, 0u, 0u), lo = make_uint4(0u, 0u, 0u, 0u);
    if (v < VOCAB) {
        float4 a = __ldg(&W4[v * 32 + q * 2]);
        float4 b = __ldg(&W4[v * 32 + q * 2 + 1]);
        __nv_bfloat16 h0, h1, l0, l1;
        split1(a.x, h0, l0); split1(a.y, h1, l1);
        hi.x = packbf(h0, h1); lo.x = packbf(l0, l1);
        split1(a.z, h0, l0); split1(a.w, h1, l1);
        hi.y = packbf(h0, h1); lo.y = packbf(l0, l1);
        split1(b.x, h0, l0); split1(b.y, h1, l1);
        hi.z = packbf(h0, h1); lo.z = packbf(l0, l1);
        split1(b.z, h0, l0); split1(b.w, h1, l1);
        hi.w = packbf(h0, h1); lo.w = packbf(l0, l1);
    }
    g_whi[idx] = hi;
    g_wlo[idx] = lo;
}

// ---------------------------------------------------------------------------
// Kernel 1 (FUSED, 512 threads): embeddings + 3 hops, one block per batch.
// (unchanged from passing R12 version)
// ---------------------------------------------------------------------------
__global__ void __launch_bounds__(512, 1) fused_kernel(
        const int* __restrict__ stories,
        const int* __restrict__ questions,
        const int* __restrict__ masks,
        const float4* __restrict__ WA4,
        const float4* __restrict__ WB4,
        const float4* __restrict__ WC4,
        const float4* __restrict__ WAT4,
        const float4* __restrict__ WCT4) {
    extern __shared__ float fsm[];
    float* m_s = fsm + FS_M;
    float* c_s = fsm + FS_C;
    float* u_s = fsm + FS_U;
    float* sc  = fsm + FS_SC;
    float* os  = fsm + FS_OS;

    int b = blockIdx.x;
    int tid = threadIdx.x;
    int w = tid >> 5, lane = tid & 31;

    for (int s = w; s < NSENT; s += 16) {
        int tk_l = 0, mz = 1;
        if (lane < TC) {
            tk_l = stories[(b * NSENT + s) * TC + lane];
            mz = masks[(b * NSENT + s) * TC + lane];
        }
        unsigned bal = __ballot_sync(0xffffffffu, (lane < TC) && (mz == 0));
        int te = bal ? (s + 1) : 0;
        float4 ma = WAT4[te * 32 + lane];
        float4 ca = WCT4[te * 32 + lane];
#pragma unroll
        for (int c0 = 0; c0 < TC; c0 += 10) {
            float4 ab[10], cb2[10];
#pragma unroll
            for (int i = 0; i < 10; ++i) {
                int tk = __shfl_sync(0xffffffffu, tk_l, c0 + i);
                ab[i]  = __ldg(&WA4[tk * 32 + lane]);
                cb2[i] = __ldg(&WC4[tk * 32 + lane]);
            }
#pragma unroll
            for (int i = 0; i < 10; ++i) {
                ma.x += ab[i].x;  ma.y += ab[i].y;  ma.z += ab[i].z;  ma.w += ab[i].w;
                ca.x += cb2[i].x; ca.y += cb2[i].y; ca.z += cb2[i].z; ca.w += cb2[i].w;
            }
        }
        ((float4*)m_s)[s * 32 + lane] = ma;
        ((float4*)c_s)[s * 32 + lane] = ca;
    }
    if (w == 15) {
        int tk_l = (lane < TC) ? questions[b * TC + lane] : 0;
        float4 ua = make_float4(0.f, 0.f, 0.f, 0.f);
#pragma unroll
        for (int c0 = 0; c0 < TC; c0 += 10) {
            float4 qb[10];
#pragma unroll
            for (int i = 0; i < 10; ++i) {
                int tk = __shfl_sync(0xffffffffu, tk_l, c0 + i);
                qb[i] = __ldg(&WB4[tk * 32 + lane]);
            }
#pragma unroll
            for (int i = 0; i < 10; ++i) {
                ua.x += qb[i].x; ua.y += qb[i].y; ua.z += qb[i].z; ua.w += qb[i].w;
            }
        }
        ((float4*)u_s)[lane] = ua;
    }
    __syncthreads();

    const int gstart[4] = {0, 13, 26, 38};
    const int gend[4]   = {13, 26, 38, 50};
    int grp = tid >> 7;
    int d = tid & 127;

    for (int hop = 0; hop < 3; ++hop) {
        for (int s = w; s < NSENT; s += 16) {
            float p = 0.f;
#pragma unroll
            for (int j = 0; j < 4; ++j) {
                int dd = lane + 32 * j;
                p += m_s[s * EMBED + dd] * u_s[dd];
            }
#pragma unroll
            for (int off = 16; off; off >>= 1)
                p += __shfl_down_sync(0xffffffffu, p, off);
            if (lane == 0) sc[s] = p;
        }
        __syncthreads();
        if (w == 0) {
            float x0 = sc[lane];
            float x1 = (lane + 32 < NSENT) ? sc[lane + 32] : -1e30f;
            float mx = fmaxf(x0, x1);
#pragma unroll
            for (int off = 16; off; off >>= 1)
                mx = fmaxf(mx, __shfl_xor_sync(0xffffffffu, mx, off));
            float e0 = expf(x0 - mx);
            float e1 = (lane + 32 < NSENT) ? expf(x1 - mx) : 0.f;
            float sm = e0 + e1;
#pragma unroll
            for (int off = 16; off; off >>= 1)
                sm += __shfl_xor_sync(0xffffffffu, sm, off);
            float inv = 1.f / sm;
            sc[lane] = e0 * inv;
            if (lane + 32 < NSENT) sc[lane + 32] = e1 * inv;
        }
        __syncthreads();
        {
            float o = 0.f;
            for (int s = gstart[grp]; s < gend[grp]; ++s)
                o += c_s[s * EMBED + d] * sc[s];
            os[grp * EMBED + d] = o;
        }
        __syncthreads();
        if (tid < EMBED) {
            u_s[tid] += os[tid] + os[EMBED + tid]
                      + os[2 * EMBED + tid] + os[3 * EMBED + tid];
        }
        __syncthreads();
    }

    if (tid < 64) {
        float a = u_s[2 * tid], c = u_s[2 * tid + 1];
        __nv_bfloat16 ah, al, ch, cl;
        split1(a, ah, al);
        split1(c, ch, cl);
        g_uhi[b * 64 + tid] = packbf(ah, ch);
        g_ulo[b * 64 + tid] = packbf(al, cl);
    }
}

// ---------------------------------------------------------------------------
// Kernel 2 (v5): GEMM. cp.async staging from pre-split bf16 globals (no
// conversion, no LDG latency chain); 8 warps as 4(m) x 2(n), warp tile
// 32x32, fused 3-term inner loop (8 ldsm + 24 mma per k-step per warp).
// ---------------------------------------------------------------------------
__global__ void __launch_bounds__(256, 2) linear_mma_kernel(
        const float* __restrict__ bias,
        float* __restrict__ out) {
    extern __shared__ char smem[];
    const uint32_t sbase = smem_u32(smem);
    int tid = threadIdx.x;
    int w = tid >> 5, lane = tid & 31;
    int wm = w >> 1, wn = w & 1;
    int v0 = blockIdx.x * TILE_M;

    // ---- cp.async A tiles: 4096 chunks (hi+lo), padded source -> no guard ----
#pragma unroll
    for (int i = 0; i < 16; ++i) {
        int idx = tid + 256 * i;
        int buf = idx >> 11;
        int r = (idx >> 4) & 127;
        int q = idx & 15;
        const uint4* src = (buf ? g_wlo : g_whi) + ((size_t)(v0 + r) * 16 + q);
        uint32_t dst = sbase + (buf ? SM_ALO : SM_AHI) + r * ROWB + q * 16;
        CPA(dst, src);
    }
    // ---- cp.async U tiles: 2048 chunks ----
#pragma unroll
    for (int i = 0; i < 8; ++i) {
        int idx = tid + 256 * i;
        int buf = idx >> 10;
        int c = idx & 1023;
        int r = c >> 4, q = c & 15;
        const uint4* src = (const uint4*)(buf ? g_ulo : g_uhi) + ((size_t)r * 16 + q);
        uint32_t dst = sbase + (buf ? SM_ULO : SM_UHI) + r * ROWB + q * 16;
        CPA(dst, src);
    }
    CPCOMMIT();
    // bias via guarded LDG, overlaps the cp.async wait
    if (tid < TILE_M) {
        int gv = v0 + tid;
        ((float*)(smem + SM_BIAS))[tid] = (gv < VOCAB) ? __ldg(&bias[gv]) : 0.f;
    }
    CPWAIT0();
    __syncthreads();

    // ---- ldmatrix lane offsets ----
    int ar = lane & 15;
    int ac = (lane >> 4) * 8;
    int br = (lane & 7) + ((lane & 16) ? 8 : 0);
    int bc = ((lane >> 3) & 1) * 8;
    uint32_t aoff0 = (uint32_t)((32 * wm + ar) * ROWB + ac * 2);
    uint32_t aoff1 = aoff0 + 16 * ROWB;
    uint32_t boff0 = (uint32_t)((32 * wn + br) * ROWB + bc * 2);
    uint32_t boff1 = boff0 + 16 * ROWB;

    float acc[2][4][4];
#pragma unroll
    for (int mi = 0; mi < 2; ++mi)
#pragma unroll
        for (int j = 0; j < 4; ++j)
#pragma unroll
            for (int q = 0; q < 4; ++q) acc[mi][j][q] = 0.f;

#pragma unroll
    for (int ks = 0; ks < 8; ++ks) {
        uint32_t k2 = (uint32_t)(ks * 32);
        uint32_t AH[8], AL[8], BH[8], BL[8];
        ldsm_x4(AH[0], AH[1], AH[2], AH[3], sbase + SM_AHI + aoff0 + k2);
        ldsm_x4(AH[4], AH[5], AH[6], AH[7], sbase + SM_AHI + aoff1 + k2);
        ldsm_x4(AL[0], AL[1], AL[2], AL[3], sbase + SM_ALO + aoff0 + k2);
        ldsm_x4(AL[4], AL[5], AL[6], AL[7], sbase + SM_ALO + aoff1 + k2);
        ldsm_x4(BH[0], BH[1], BH[2], BH[3], sbase + SM_UHI + boff0 + k2);
        ldsm_x4(BH[4], BH[5], BH[6], BH[7], sbase + SM_UHI + boff1 + k2);
        ldsm_x4(BL[0], BL[1], BL[2], BL[3], sbase + SM_ULO + boff0 + k2);
        ldsm_x4(BL[4], BL[5], BL[6], BL[7], sbase + SM_ULO + boff1 + k2);
#pragma unroll
        for (int mi = 0; mi < 2; ++mi) {
#pragma unroll
            for (int j = 0; j < 4; ++j) {
                mma16816(acc[mi][j], &AH[4 * mi], &BH[2 * j]);   // hi*hi
                mma16816(acc[mi][j], &AH[4 * mi], &BL[2 * j]);   // hi*lo
                mma16816(acc[mi][j], &AL[4 * mi], &BH[2 * j]);   // lo*hi
            }
        }
    }

    // ---- epilogue: transpose via smem (stride 67), then consecutive-v stores ----
    __syncthreads();
    {
        float* smemT = (float*)smem;          // 128 x 67 floats, reuses A region
        int mrow = lane >> 2;
        int ncol = (lane & 3) * 2;
#pragma unroll
        for (int mi = 0; mi < 2; ++mi) {
            int va = 32 * wm + 16 * mi + mrow;
            int vb = va + 8;
#pragma unroll
            for (int j = 0; j < 4; ++j) {
                int b0 = 32 * wn + 8 * j + ncol;
                smemT[va * 67 + b0]     = acc[mi][j][0];
                smemT[va * 67 + b0 + 1] = acc[mi][j][1];
                smemT[vb * 67 + b0]     = acc[mi][j][2];
                smemT[vb * 67 + b0 + 1] = acc[mi][j][3];
            }
        }
        __syncthreads();
        const float* bias_s = (const float*)(smem + SM_BIAS);
        for (int bb = w; bb < BATCH; bb += 8) {
            size_t rowbase = (size_t)bb * VOCAB;
#pragma unroll
            for (int vh = 0; vh < 4; ++vh) {
                int vl = vh * 32 + lane;
                int v = v0 + vl;
                if (v < VOCAB)
                    out[rowbase + v] = smemT[vl * 67 + bb] + bias_s[vl];
            }
        }
    }
}

// ---------------------------------------------------------------------------
extern "C" void kernel_launch(void* const* d_in, const int* in_sizes, int n_in,
                              void* d_out, int out_size) {
    const int*   stories   = (const int*)d_in[0];
    const int*   questions = (const int*)d_in[1];
    const int*   masks     = (const int*)d_in[2];
    const float* WA        = (const float*)d_in[3];
    const float* WB        = (const float*)d_in[4];
    const float* WC        = (const float*)d_in[5];
    const float* WAT       = (const float*)d_in[6];
    const float* WCT       = (const float*)d_in[7];
    const float* Wlin      = (const float*)d_in[8];
    const float* blin      = (const float*)d_in[9];
    float* out = (float*)d_out;

    cudaFuncSetAttribute(fused_kernel,
                         cudaFuncAttributeMaxDynamicSharedMemorySize, FS_TOTB);
    cudaFuncSetAttribute(linear_mma_kernel,
                         cudaFuncAttributeMaxDynamicSharedMemorySize, SM_TOT);

    fused_kernel<<<BATCH, 512, FS_TOTB>>>(stories, questions, masks,
                                          (const float4*)WA, (const float4*)WB,
                                          (const float4*)WC, (const float4*)WAT,
                                          (const float4*)WCT);
    wsplit_kernel<<<VPAD * 16 / 256, 256>>>((const float4*)Wlin);   // 3144 blocks
    linear_mma_kernel<<<NBLK, 256, SM_TOT>>>(blin, out);
}

// round 14
// speedup vs baseline: 1.1676x; 1.1676x over previous
#include <cuda_runtime.h>
#include <cuda_bf16.h>
#include <cstdint>

#define VOCAB 50257
#define EMBED 128
#define BATCH 64
#define NSENT 50
#define TC 20

#define TILE_M 128
#define NBLK ((VOCAB + TILE_M - 1) / TILE_M)   // 393

// padded row stride for conflict-free ldmatrix: 272B = 17 x 16B
#define ROWB 272

// GEMM smem layout (bytes)
#define SM_AHI 0
#define SM_ALO (SM_AHI + TILE_M * ROWB)     // 34816
#define SM_UHI (SM_ALO + TILE_M * ROWB)     // 69632
#define SM_ULO (SM_UHI + BATCH * ROWB)      // 87040
#define SM_BIAS (SM_ULO + BATCH * ROWB)     // 104448
#define SM_TOT (SM_BIAS + 512)              // 104960 -> 2 CTAs/SM
// fp32 W staging scratch: overlays the U region (released before U loads)
#define SM_SCR SM_UHI                        // 2 x 16384 B double buffer

// fused kernel smem (floats)
#define FS_M 0
#define FS_C (NSENT * EMBED)
#define FS_U (FS_C + NSENT * EMBED)
#define FS_SC (FS_U + EMBED)
#define FS_OS (FS_SC + 64)
#define FS_TOTF (FS_OS + 4 * EMBED)
#define FS_TOTB (FS_TOTF * 4)               // 54016 B

// device scratch
__device__ uint32_t g_uhi[BATCH * 64];      // u hi, [b][64 x uint32(k,k+1)]
__device__ uint32_t g_ulo[BATCH * 64];

// ---------------------------------------------------------------------------
// helpers
// ---------------------------------------------------------------------------
__device__ __forceinline__ uint32_t smem_u32(const void* p) {
    uint32_t a;
    asm("{ .reg .u64 t; cvta.to.shared.u64 t, %1; cvt.u32.u64 %0, t; }"
        : "=r"(a) : "l"(p));
    return a;
}
__device__ __forceinline__ void ldsm_x4(uint32_t& r0, uint32_t& r1,
                                        uint32_t& r2, uint32_t& r3, uint32_t a) {
    asm volatile("ldmatrix.sync.aligned.m8n8.x4.shared.b16 {%0,%1,%2,%3}, [%4];"
                 : "=r"(r0), "=r"(r1), "=r"(r2), "=r"(r3) : "r"(a));
}
__device__ __forceinline__ void mma16816(float* d, const uint32_t* a,
                                         const uint32_t* b) {
    asm volatile(
        "mma.sync.aligned.m16n8k16.row.col.f32.bf16.bf16.f32 "
        "{%0,%1,%2,%3}, {%4,%5,%6,%7}, {%8,%9}, {%0,%1,%2,%3};"
        : "+f"(d[0]), "+f"(d[1]), "+f"(d[2]), "+f"(d[3])
        : "r"(a[0]), "r"(a[1]), "r"(a[2]), "r"(a[3]), "r"(b[0]), "r"(b[1]));
}
__device__ __forceinline__ uint32_t packbf(__nv_bfloat16 lo, __nv_bfloat16 hi) {
    return ((uint32_t)__bfloat16_as_ushort(hi) << 16)
         | (uint32_t)__bfloat16_as_ushort(lo);
}
__device__ __forceinline__ void split1(float x, __nv_bfloat16& h, __nv_bfloat16& l) {
    h = __float2bfloat16_rn(x);
    l = __float2bfloat16_rn(x - __bfloat162float(h));
}
#define CPA(dst, src) \
    asm volatile("cp.async.cg.shared.global [%0], [%1], 16;" \
                 :: "r"(dst), "l"(src) : "memory")
#define CPAZ(dst, src, sz) \
    asm volatile("cp.async.cg.shared.global [%0], [%1], 16, %2;" \
                 :: "r"(dst), "l"(src), "r"(sz) : "memory")
#define CPCOMMIT() asm volatile("cp.async.commit_group;" ::: "memory")
#define CPWAIT(n)  asm volatile("cp.async.wait_group %0;" :: "n"(n) : "memory")

// ---------------------------------------------------------------------------
// Kernel 1 (FUSED, 512 threads): embeddings + 3 hops, one block per batch.
// (unchanged from passing R12/R13 version)
// ---------------------------------------------------------------------------
__global__ void __launch_bounds__(512, 1) fused_kernel(
        const int* __restrict__ stories,
        const int* __restrict__ questions,
        const int* __restrict__ masks,
        const float4* __restrict__ WA4,
        const float4* __restrict__ WB4,
        const float4* __restrict__ WC4,
        const float4* __restrict__ WAT4,
        const float4* __restrict__ WCT4) {
    extern __shared__ float fsm[];
    float* m_s = fsm + FS_M;
    float* c_s = fsm + FS_C;
    float* u_s = fsm + FS_U;
    float* sc  = fsm + FS_SC;
    float* os  = fsm + FS_OS;

    int b = blockIdx.x;
    int tid = threadIdx.x;
    int w = tid >> 5, lane = tid & 31;

    for (int s = w; s < NSENT; s += 16) {
        int tk_l = 0, mz = 1;
        if (lane < TC) {
            tk_l = stories[(b * NSENT + s) * TC + lane];
            mz = masks[(b * NSENT + s) * TC + lane];
        }
        unsigned bal = __ballot_sync(0xffffffffu, (lane < TC) && (mz == 0));
        int te = bal ? (s + 1) : 0;
        float4 ma = WAT4[te * 32 + lane];
        float4 ca = WCT4[te * 32 + lane];
#pragma unroll
        for (int c0 = 0; c0 < TC; c0 += 10) {
            float4 ab[10], cb2[10];
#pragma unroll
            for (int i = 0; i < 10; ++i) {
                int tk = __shfl_sync(0xffffffffu, tk_l, c0 + i);
                ab[i]  = __ldg(&WA4[tk * 32 + lane]);
                cb2[i] = __ldg(&WC4[tk * 32 + lane]);
            }
#pragma unroll
            for (int i = 0; i < 10; ++i) {
                ma.x += ab[i].x;  ma.y += ab[i].y;  ma.z += ab[i].z;  ma.w += ab[i].w;
                ca.x += cb2[i].x; ca.y += cb2[i].y; ca.z += cb2[i].z; ca.w += cb2[i].w;
            }
        }
        ((float4*)m_s)[s * 32 + lane] = ma;
        ((float4*)c_s)[s * 32 + lane] = ca;
    }
    if (w == 15) {
        int tk_l = (lane < TC) ? questions[b * TC + lane] : 0;
        float4 ua = make_float4(0.f, 0.f, 0.f, 0.f);
#pragma unroll
        for (int c0 = 0; c0 < TC; c0 += 10) {
            float4 qb[10];
#pragma unroll
            for (int i = 0; i < 10; ++i) {
                int tk = __shfl_sync(0xffffffffu, tk_l, c0 + i);
                qb[i] = __ldg(&WB4[tk * 32 + lane]);
            }
#pragma unroll
            for (int i = 0; i < 10; ++i) {
                ua.x += qb[i].x; ua.y += qb[i].y; ua.z += qb[i].z; ua.w += qb[i].w;
            }
        }
        ((float4*)u_s)[lane] = ua;
    }
    __syncthreads();

    const int gstart[4] = {0, 13, 26, 38};
    const int gend[4]   = {13, 26, 38, 50};
    int grp = tid >> 7;
    int d = tid & 127;

    for (int hop = 0; hop < 3; ++hop) {
        for (int s = w; s < NSENT; s += 16) {
            float p = 0.f;
#pragma unroll
            for (int j = 0; j < 4; ++j) {
                int dd = lane + 32 * j;
                p += m_s[s * EMBED + dd] * u_s[dd];
            }
#pragma unroll
            for (int off = 16; off; off >>= 1)
                p += __shfl_down_sync(0xffffffffu, p, off);
            if (lane == 0) sc[s] = p;
        }
        __syncthreads();
        if (w == 0) {
            float x0 = sc[lane];
            float x1 = (lane + 32 < NSENT) ? sc[lane + 32] : -1e30f;
            float mx = fmaxf(x0, x1);
#pragma unroll
            for (int off = 16; off; off >>= 1)
                mx = fmaxf(mx, __shfl_xor_sync(0xffffffffu, mx, off));
            float e0 = expf(x0 - mx);
            float e1 = (lane + 32 < NSENT) ? expf(x1 - mx) : 0.f;
            float sm = e0 + e1;
#pragma unroll
            for (int off = 16; off; off >>= 1)
                sm += __shfl_xor_sync(0xffffffffu, sm, off);
            float inv = 1.f / sm;
            sc[lane] = e0 * inv;
            if (lane + 32 < NSENT) sc[lane + 32] = e1 * inv;
        }
        __syncthreads();
        {
            float o = 0.f;
            for (int s = gstart[grp]; s < gend[grp]; ++s)
                o += c_s[s * EMBED + d] * sc[s];
            os[grp * EMBED + d] = o;
        }
        __syncthreads();
        if (tid < EMBED) {
            u_s[tid] += os[tid] + os[EMBED + tid]
                      + os[2 * EMBED + tid] + os[3 * EMBED + tid];
        }
        __syncthreads();
    }

    if (tid < 64) {
        float a = u_s[2 * tid], c = u_s[2 * tid + 1];
        __nv_bfloat16 ah, al, ch, cl;
        split1(a, ah, al);
        split1(c, ch, cl);
        g_uhi[b * 64 + tid] = packbf(ah, ch);
        g_ulo[b * 64 + tid] = packbf(al, cl);
    }
}

// ---------------------------------------------------------------------------
// Kernel 2 (v6): GEMM with IN-KERNEL W split fed by cp.async.
// W fp32 staged in 4 chunks of 32 rows (16KB) through a 2x16KB smem double
// buffer overlaying the (not-yet-loaded) U region; each chunk: wait -> regs
// -> sync -> prefetch chunk c+2 -> split to bf16 hi/lo A tiles. OOB tail
// rows zero-filled via cp.async src-size=0. U tiles cp.async'd after the
// scratch is released. Mainloop/epilogue = proven R13 structure.
// ---------------------------------------------------------------------------
__global__ void __launch_bounds__(256, 2) linear_mma_kernel(
        const float* __restrict__ W,
        const float* __restrict__ bias,
        float* __restrict__ out) {
    extern __shared__ char smem[];
    const uint32_t sbase = smem_u32(smem);
    int tid = threadIdx.x;
    int w = tid >> 5, lane = tid & 31;
    int wm = w >> 1, wn = w & 1;
    int v0 = blockIdx.x * TILE_M;

    // per-thread slice of a 32-row chunk: 64B of one row
    int crow = tid >> 3;          // 0..31
    int csub = tid & 7;           // 64B sub-offset within 512B row

    // ---- issue W chunks 0,1 into double buffer ----
#define ISSUE_CHUNK(c)                                                        \
    {                                                                         \
        int gv = v0 + 32 * (c) + crow;                                        \
        const char* src = (const char*)W + (size_t)gv * 512 + csub * 64;      \
        uint32_t dst = sbase + SM_SCR + ((c) & 1) * 16384 + crow * 512        \
                     + csub * 64;                                             \
        int sz = (gv < VOCAB) ? 16 : 0;                                       \
        CPAZ(dst, src, sz);                                                   \
        CPAZ(dst + 16, src + 16, sz);                                         \
        CPAZ(dst + 32, src + 32, sz);                                         \
        CPAZ(dst + 48, src + 48, sz);                                         \
        CPCOMMIT();                                                           \
    }
    ISSUE_CHUNK(0)
    ISSUE_CHUNK(1)

    // bias (guarded LDG) overlaps the first cp.async wait
    if (tid < TILE_M) {
        int gv = v0 + tid;
        ((float*)(smem + SM_BIAS))[tid] = (gv < VOCAB) ? __ldg(&bias[gv]) : 0.f;
    }

    // ---- 4 chunks: wait -> regs -> sync -> prefetch -> split into A tiles ----
#define CONVERT_CHUNK(c, WAITN, PREFETCH)                                     \
    {                                                                         \
        CPWAIT(WAITN);                                                        \
        __syncthreads();                                                      \
        const float4* s4 = (const float4*)(smem + SM_SCR + ((c) & 1) * 16384  \
                                           + crow * 512 + csub * 64);         \
        float4 f0 = s4[0], f1 = s4[1], f2 = s4[2], f3 = s4[3];                \
        __syncthreads();                                                      \
        PREFETCH                                                              \
        int arow = 32 * (c) + crow;                                           \
        uint4* dh = (uint4*)(smem + SM_AHI + arow * ROWB + csub * 32);        \
        uint4* dl = (uint4*)(smem + SM_ALO + arow * ROWB + csub * 32);        \
        __nv_bfloat16 h0, h1, l0, l1;                                         \
        uint4 H, L;                                                           \
        split1(f0.x, h0, l0); split1(f0.y, h1, l1);                           \
        H.x = packbf(h0, h1); L.x = packbf(l0, l1);                           \
        split1(f0.z, h0, l0); split1(f0.w, h1, l1);                           \
        H.y = packbf(h0, h1); L.y = packbf(l0, l1);                           \
        split1(f1.x, h0, l0); split1(f1.y, h1, l1);                           \
        H.z = packbf(h0, h1); L.z = packbf(l0, l1);                           \
        split1(f1.z, h0, l0); split1(f1.w, h1, l1);                           \
        H.w = packbf(h0, h1); L.w = packbf(l0, l1);                           \
        dh[0] = H; dl[0] = L;                                                 \
        split1(f2.x, h0, l0); split1(f2.y, h1, l1);                           \
        H.x = packbf(h0, h1); L.x = packbf(l0, l1);                           \
        split1(f2.z, h0, l0); split1(f2.w, h1, l1);                           \
        H.y = packbf(h0, h1); L.y = packbf(l0, l1);                           \
        split1(f3.x, h0, l0); split1(f3.y, h1, l1);                           \
        H.z = packbf(h0, h1); L.z = packbf(l0, l1);                           \
        split1(f3.z, h0, l0); split1(f3.w, h1, l1);                           \
        H.w = packbf(h0, h1); L.w = packbf(l0, l1);                           \
        dh[1] = H; dl[1] = L;                                                 \
    }
    CONVERT_CHUNK(0, 1, ISSUE_CHUNK(2))
    CONVERT_CHUNK(1, 1, ISSUE_CHUNK(3))
    CONVERT_CHUNK(2, 1, )
    CONVERT_CHUNK(3, 0, )

    // ---- scratch now free: cp.async U tiles (2048 x 16B over 256 thr) ----
    __syncthreads();     // all scratch reads done before overwrite
#pragma unroll
    for (int i = 0; i < 8; ++i) {
        int idx = tid + 256 * i;
        int buf = idx >> 10;
        int c2 = idx & 1023;
        int r = c2 >> 4, q = c2 & 15;
        const uint4* src = (const uint4*)(buf ? g_ulo : g_uhi) + ((size_t)r * 16 + q);
        uint32_t dst = sbase + (buf ? SM_ULO : SM_UHI) + r * ROWB + q * 16;
        CPA(dst, src);
    }
    CPCOMMIT();
    CPWAIT(0);
    __syncthreads();

    // ---- ldmatrix lane offsets ----
    int ar = lane & 15;
    int ac = (lane >> 4) * 8;
    int br = (lane & 7) + ((lane & 16) ? 8 : 0);
    int bc = ((lane >> 3) & 1) * 8;
    uint32_t aoff0 = (uint32_t)((32 * wm + ar) * ROWB + ac * 2);
    uint32_t aoff1 = aoff0 + 16 * ROWB;
    uint32_t boff0 = (uint32_t)((32 * wn + br) * ROWB + bc * 2);
    uint32_t boff1 = boff0 + 16 * ROWB;

    float acc[2][4][4];
#pragma unroll
    for (int mi = 0; mi < 2; ++mi)
#pragma unroll
        for (int j = 0; j < 4; ++j)
#pragma unroll
            for (int q = 0; q < 4; ++q) acc[mi][j][q] = 0.f;

#pragma unroll
    for (int ks = 0; ks < 8; ++ks) {
        uint32_t k2 = (uint32_t)(ks * 32);
        uint32_t AH[8], AL[8], BH[8], BL[8];
        ldsm_x4(AH[0], AH[1], AH[2], AH[3], sbase + SM_AHI + aoff0 + k2);
        ldsm_x4(AH[4], AH[5], AH[6], AH[7], sbase + SM_AHI + aoff1 + k2);
        ldsm_x4(AL[0], AL[1], AL[2], AL[3], sbase + SM_ALO + aoff0 + k2);
        ldsm_x4(AL[4], AL[5], AL[6], AL[7], sbase + SM_ALO + aoff1 + k2);
        ldsm_x4(BH[0], BH[1], BH[2], BH[3], sbase + SM_UHI + boff0 + k2);
        ldsm_x4(BH[4], BH[5], BH[6], BH[7], sbase + SM_UHI + boff1 + k2);
        ldsm_x4(BL[0], BL[1], BL[2], BL[3], sbase + SM_ULO + boff0 + k2);
        ldsm_x4(BL[4], BL[5], BL[6], BL[7], sbase + SM_ULO + boff1 + k2);
#pragma unroll
        for (int mi = 0; mi < 2; ++mi) {
#pragma unroll
            for (int j = 0; j < 4; ++j) {
                mma16816(acc[mi][j], &AH[4 * mi], &BH[2 * j]);   // hi*hi
                mma16816(acc[mi][j], &AH[4 * mi], &BL[2 * j]);   // hi*lo
                mma16816(acc[mi][j], &AL[4 * mi], &BH[2 * j]);   // lo*hi
            }
        }
    }

    // ---- epilogue: transpose via smem (stride 67), consecutive-v stores ----
    __syncthreads();
    {
        float* smemT = (float*)smem;          // 128 x 67 floats, reuses A region
        int mrow = lane >> 2;
        int ncol = (lane & 3) * 2;
#pragma unroll
        for (int mi = 0; mi < 2; ++mi) {
            int va = 32 * wm + 16 * mi + mrow;
            int vb = va + 8;
#pragma unroll
            for (int j = 0; j < 4; ++j) {
                int b0 = 32 * wn + 8 * j + ncol;
                smemT[va * 67 + b0]     = acc[mi][j][0];
                smemT[va * 67 + b0 + 1] = acc[mi][j][1];
                smemT[vb * 67 + b0]     = acc[mi][j][2];
                smemT[vb * 67 + b0 + 1] = acc[mi][j][3];
            }
        }
        __syncthreads();
        const float* bias_s = (const float*)(smem + SM_BIAS);
        for (int bb = w; bb < BATCH; bb += 8) {
            size_t rowbase = (size_t)bb * VOCAB;
#pragma unroll
            for (int vh = 0; vh < 4; ++vh) {
                int vl = vh * 32 + lane;
                int v = v0 + vl;
                if (v < VOCAB)
                    out[rowbase + v] = smemT[vl * 67 + bb] + bias_s[vl];
            }
        }
    }
}

// ---------------------------------------------------------------------------
extern "C" void kernel_launch(void* const* d_in, const int* in_sizes, int n_in,
                              void* d_out, int out_size) {
    const int*   stories   = (const int*)d_in[0];
    const int*   questions = (const int*)d_in[1];
    const int*   masks     = (const int*)d_in[2];
    const float* WA        = (const float*)d_in[3];
    const float* WB        = (const float*)d_in[4];
    const float* WC        = (const float*)d_in[5];
    const float* WAT       = (const float*)d_in[6];
    const float* WCT       = (const float*)d_in[7];
    const float* Wlin      = (const float*)d_in[8];
    const float* blin      = (const float*)d_in[9];
    float* out = (float*)d_out;

    cudaFuncSetAttribute(fused_kernel,
                         cudaFuncAttributeMaxDynamicSharedMemorySize, FS_TOTB);
    cudaFuncSetAttribute(linear_mma_kernel,
                         cudaFuncAttributeMaxDynamicSharedMemorySize, SM_TOT);

    fused_kernel<<<BATCH, 512, FS_TOTB>>>(stories, questions, masks,
                                          (const float4*)WA, (const float4*)WB,
                                          (const float4*)WC, (const float4*)WAT,
                                          (const float4*)WCT);
    linear_mma_kernel<<<NBLK, 256, SM_TOT>>>(Wlin, blin, out);
}

// round 15
// speedup vs baseline: 1.2916x; 1.1062x over previous
#include <cuda_runtime.h>
#include <cuda_bf16.h>
#include <cstdint>

#define VOCAB 50257
#define EMBED 128
#define BATCH 64
#define NSENT 50
#define TC 20

#define TILE_M 128
#define NBLK ((VOCAB + TILE_M - 1) / TILE_M)   // 393

// padded row stride for conflict-free ldmatrix: 272B = 17 x 16B
#define ROWB 272

// GEMM smem layout (bytes)
#define SM_AHI 0
#define SM_ALO (SM_AHI + TILE_M * ROWB)     // 34816
#define SM_UHI (SM_ALO + TILE_M * ROWB)     // 69632
#define SM_ULO (SM_UHI + BATCH * ROWB)      // 87040
#define SM_BIAS (SM_ULO + BATCH * ROWB)     // 104448
#define SM_MB  (SM_BIAS + 512)              // 104960: 3 mbarriers
#define SM_TOT (SM_MB + 48)                 // 105008 -> still 2 CTAs/SM
// fp32 W staging scratch: overlays the U region (released before U loads)
#define SM_SCR SM_UHI                        // 2 x 16384 B double buffer

// fused kernel smem (floats)
#define FS_M 0
#define FS_C (NSENT * EMBED)
#define FS_U (FS_C + NSENT * EMBED)
#define FS_SC (FS_U + EMBED)
#define FS_OS (FS_SC + 64)
#define FS_TOTF (FS_OS + 4 * EMBED)
#define FS_TOTB (FS_TOTF * 4)               // 54016 B

// u after hops, bf16 hi/lo, PADDED GEMM smem image: 64 rows x 272B
__device__ uint4 g_upadh4[BATCH * ROWB / 16];   // 1088 x 16B
__device__ uint4 g_upadl4[BATCH * ROWB / 16];

// ---------------------------------------------------------------------------
// helpers
// ---------------------------------------------------------------------------
__device__ __forceinline__ uint32_t smem_u32(const void* p) {
    uint32_t a;
    asm("{ .reg .u64 t; cvta.to.shared.u64 t, %1; cvt.u32.u64 %0, t; }"
        : "=r"(a) : "l"(p));
    return a;
}
__device__ __forceinline__ void ldsm_x4(uint32_t& r0, uint32_t& r1,
                                        uint32_t& r2, uint32_t& r3, uint32_t a) {
    asm volatile("ldmatrix.sync.aligned.m8n8.x4.shared.b16 {%0,%1,%2,%3}, [%4];"
                 : "=r"(r0), "=r"(r1), "=r"(r2), "=r"(r3) : "r"(a));
}
__device__ __forceinline__ void mma16816(float* d, const uint32_t* a,
                                         const uint32_t* b) {
    asm volatile(
        "mma.sync.aligned.m16n8k16.row.col.f32.bf16.bf16.f32 "
        "{%0,%1,%2,%3}, {%4,%5,%6,%7}, {%8,%9}, {%0,%1,%2,%3};"
        : "+f"(d[0]), "+f"(d[1]), "+f"(d[2]), "+f"(d[3])
        : "r"(a[0]), "r"(a[1]), "r"(a[2]), "r"(a[3]), "r"(b[0]), "r"(b[1]));
}
__device__ __forceinline__ uint32_t packbf(__nv_bfloat16 lo, __nv_bfloat16 hi) {
    return ((uint32_t)__bfloat16_as_ushort(hi) << 16)
         | (uint32_t)__bfloat16_as_ushort(lo);
}
__device__ __forceinline__ void split1(float x, __nv_bfloat16& h, __nv_bfloat16& l) {
    h = __float2bfloat16_rn(x);
    l = __float2bfloat16_rn(x - __bfloat162float(h));
}
// 16B cp.async (tail-CTA fallback path only)
#define CPAZ(dst, src, sz) \
    asm volatile("cp.async.cg.shared.global [%0], [%1], 16, %2;" \
                 :: "r"(dst), "l"(src), "r"(sz) : "memory")
#define CPCOMMIT() asm volatile("cp.async.commit_group;" ::: "memory")
#define CPWAIT(n)  asm volatile("cp.async.wait_group %0;" :: "n"(n) : "memory")
// bulk copy + mbarrier (plain sm_90+ PTX, no arch suffix)
#define MBAR_INIT(a, c) \
    asm volatile("mbarrier.init.shared.b64 [%0], %1;" :: "r"(a), "r"(c) : "memory")
#define MBAR_EXPECT(a, n) \
    asm volatile("mbarrier.arrive.expect_tx.shared.b64 _, [%0], %1;" \
                 :: "r"(a), "r"(n) : "memory")
#define BULK_G2S(dst, src, sz, mb) \
    asm volatile("cp.async.bulk.shared::cta.global.mbarrier::complete_tx::bytes " \
                 "[%0], [%1], %2, [%3];" \
                 :: "r"(dst), "l"(src), "r"(sz), "r"(mb) : "memory")
__device__ __forceinline__ void mbar_wait(uint32_t addr, uint32_t ph) {
    asm volatile(
        "{\n\t.reg .pred P;\n"
        "W%=:\n\t"
        "mbarrier.try_wait.parity.shared.b64 P, [%0], %1;\n\t"
        "@!P bra W%=;\n\t}"
        :: "r"(addr), "r"(ph) : "memory");
}

// ---------------------------------------------------------------------------
// Kernel 1 (FUSED, 512 threads): embeddings + 3 hops, one block per batch.
// (logic unchanged; epilogue now writes the padded U image for bulk-copy)
// ---------------------------------------------------------------------------
__global__ void __launch_bounds__(512, 1) fused_kernel(
        const int* __restrict__ stories,
        const int* __restrict__ questions,
        const int* __restrict__ masks,
        const float4* __restrict__ WA4,
        const float4* __restrict__ WB4,
        const float4* __restrict__ WC4,
        const float4* __restrict__ WAT4,
        const float4* __restrict__ WCT4) {
    extern __shared__ float fsm[];
    float* m_s = fsm + FS_M;
    float* c_s = fsm + FS_C;
    float* u_s = fsm + FS_U;
    float* sc  = fsm + FS_SC;
    float* os  = fsm + FS_OS;

    int b = blockIdx.x;
    int tid = threadIdx.x;
    int w = tid >> 5, lane = tid & 31;

    for (int s = w; s < NSENT; s += 16) {
        int tk_l = 0, mz = 1;
        if (lane < TC) {
            tk_l = stories[(b * NSENT + s) * TC + lane];
            mz = masks[(b * NSENT + s) * TC + lane];
        }
        unsigned bal = __ballot_sync(0xffffffffu, (lane < TC) && (mz == 0));
        int te = bal ? (s + 1) : 0;
        float4 ma = WAT4[te * 32 + lane];
        float4 ca = WCT4[te * 32 + lane];
#pragma unroll
        for (int c0 = 0; c0 < TC; c0 += 10) {
            float4 ab[10], cb2[10];
#pragma unroll
            for (int i = 0; i < 10; ++i) {
                int tk = __shfl_sync(0xffffffffu, tk_l, c0 + i);
                ab[i]  = __ldg(&WA4[tk * 32 + lane]);
                cb2[i] = __ldg(&WC4[tk * 32 + lane]);
            }
#pragma unroll
            for (int i = 0; i < 10; ++i) {
                ma.x += ab[i].x;  ma.y += ab[i].y;  ma.z += ab[i].z;  ma.w += ab[i].w;
                ca.x += cb2[i].x; ca.y += cb2[i].y; ca.z += cb2[i].z; ca.w += cb2[i].w;
            }
        }
        ((float4*)m_s)[s * 32 + lane] = ma;
        ((float4*)c_s)[s * 32 + lane] = ca;
    }
    if (w == 15) {
        int tk_l = (lane < TC) ? questions[b * TC + lane] : 0;
        float4 ua = make_float4(0.f, 0.f, 0.f, 0.f);
#pragma unroll
        for (int c0 = 0; c0 < TC; c0 += 10) {
            float4 qb[10];
#pragma unroll
            for (int i = 0; i < 10; ++i) {
                int tk = __shfl_sync(0xffffffffu, tk_l, c0 + i);
                qb[i] = __ldg(&WB4[tk * 32 + lane]);
            }
#pragma unroll
            for (int i = 0; i < 10; ++i) {
                ua.x += qb[i].x; ua.y += qb[i].y; ua.z += qb[i].z; ua.w += qb[i].w;
            }
        }
        ((float4*)u_s)[lane] = ua;
    }
    __syncthreads();

    const int gstart[4] = {0, 13, 26, 38};
    const int gend[4]   = {13, 26, 38, 50};
    int grp = tid >> 7;
    int d = tid & 127;

    for (int hop = 0; hop < 3; ++hop) {
        for (int s = w; s < NSENT; s += 16) {
            float p = 0.f;
#pragma unroll
            for (int j = 0; j < 4; ++j) {
                int dd = lane + 32 * j;
                p += m_s[s * EMBED + dd] * u_s[dd];
            }
#pragma unroll
            for (int off = 16; off; off >>= 1)
                p += __shfl_down_sync(0xffffffffu, p, off);
            if (lane == 0) sc[s] = p;
        }
        __syncthreads();
        if (w == 0) {
            float x0 = sc[lane];
            float x1 = (lane + 32 < NSENT) ? sc[lane + 32] : -1e30f;
            float mx = fmaxf(x0, x1);
#pragma unroll
            for (int off = 16; off; off >>= 1)
                mx = fmaxf(mx, __shfl_xor_sync(0xffffffffu, mx, off));
            float e0 = expf(x0 - mx);
            float e1 = (lane + 32 < NSENT) ? expf(x1 - mx) : 0.f;
            float sm = e0 + e1;
#pragma unroll
            for (int off = 16; off; off >>= 1)
                sm += __shfl_xor_sync(0xffffffffu, sm, off);
            float inv = 1.f / sm;
            sc[lane] = e0 * inv;
            if (lane + 32 < NSENT) sc[lane + 32] = e1 * inv;
        }
        __syncthreads();
        {
            float o = 0.f;
            for (int s = gstart[grp]; s < gend[grp]; ++s)
                o += c_s[s * EMBED + d] * sc[s];
            os[grp * EMBED + d] = o;
        }
        __syncthreads();
        if (tid < EMBED) {
            u_s[tid] += os[tid] + os[EMBED + tid]
                      + os[2 * EMBED + tid] + os[3 * EMBED + tid];
        }
        __syncthreads();
    }

    // epilogue: padded U image (row b = 272B, first 256B data)
    if (tid < 64) {
        float a = u_s[2 * tid], c = u_s[2 * tid + 1];
        __nv_bfloat16 ah, al, ch, cl;
        split1(a, ah, al);
        split1(c, ch, cl);
        ((uint32_t*)g_upadh4)[b * (ROWB / 4) + tid] = packbf(ah, ch);
        ((uint32_t*)g_upadl4)[b * (ROWB / 4) + tid] = packbf(al, cl);
    }
}

// ---------------------------------------------------------------------------
// Kernel 2 (v7): GEMM. W staged via cp.async.bulk (1 instr / 16KB chunk,
// mbarrier-completed) through the 2x16KB double buffer; in-kernel bf16
// hi/lo split; U via 2 bulk copies of the padded image. Tail CTA (OOB rows)
// falls back to guarded 16B cp.async. Mainloop/epilogue = proven structure.
// ---------------------------------------------------------------------------
__global__ void __launch_bounds__(256, 2) linear_mma_kernel(
        const float* __restrict__ W,
        const float* __restrict__ bias,
        float* __restrict__ out) {
    extern __shared__ char smem[];
    const uint32_t sbase = smem_u32(smem);
    int tid = threadIdx.x;
    int w = tid >> 5, lane = tid & 31;
    int wm = w >> 1, wn = w & 1;
    int v0 = blockIdx.x * TILE_M;
    bool fullTile = (v0 + TILE_M <= VOCAB);

    uint32_t mb0 = sbase + SM_MB, mb1 = sbase + SM_MB + 16, mbU = sbase + SM_MB + 32;
    if (tid == 0) {
        MBAR_INIT(mb0, 1);
        MBAR_INIT(mb1, 1);
        MBAR_INIT(mbU, 1);
    }
    __syncthreads();

    // per-thread slice of a 32-row chunk: 64B of one row
    int crow = tid >> 3;          // 0..31
    int csub = tid & 7;           // 64B sub-offset within 512B row

    // ---- issue W chunks 0,1 ----
    if (fullTile) {
        if (tid == 0) {
            MBAR_EXPECT(mb0, 16384);
            BULK_G2S(sbase + SM_SCR, (const char*)W + (size_t)v0 * 512,
                     16384, mb0);
            MBAR_EXPECT(mb1, 16384);
            BULK_G2S(sbase + SM_SCR + 16384,
                     (const char*)W + (size_t)(v0 + 32) * 512, 16384, mb1);
        }
    } else {
#define ISSUE_CHUNK_SLOW(c)                                                   \
        {                                                                     \
            int gv = v0 + 32 * (c) + crow;                                    \
            const char* src = (const char*)W + (size_t)gv * 512 + csub * 64;  \
            uint32_t dst = sbase + SM_SCR + ((c) & 1) * 16384 + crow * 512    \
                         + csub * 64;                                         \
            int sz = (gv < VOCAB) ? 16 : 0;                                   \
            CPAZ(dst, src, sz);                                               \
            CPAZ(dst + 16, src + 16, sz);                                     \
            CPAZ(dst + 32, src + 32, sz);                                     \
            CPAZ(dst + 48, src + 48, sz);                                     \
            CPCOMMIT();                                                       \
        }
        ISSUE_CHUNK_SLOW(0)
        ISSUE_CHUNK_SLOW(1)
    }

    // bias (guarded LDG) overlaps the first wait
    if (tid < TILE_M) {
        int gv = v0 + tid;
        ((float*)(smem + SM_BIAS))[tid] = (gv < VOCAB) ? __ldg(&bias[gv]) : 0.f;
    }

    // ---- 4 chunks: wait -> regs -> sync -> issue next -> split into A ----
#define CONVERT_CHUNK(c, WAITCODE, ISSUECODE)                                 \
    {                                                                         \
        WAITCODE                                                              \
        __syncthreads();                                                      \
        const float4* s4 = (const float4*)(smem + SM_SCR + ((c) & 1) * 16384  \
                                           + crow * 512 + csub * 64);         \
        float4 f0 = s4[0], f1 = s4[1], f2 = s4[2], f3 = s4[3];                \
        __syncthreads();                                                      \
        ISSUECODE                                                             \
        int arow = 32 * (c) + crow;                                           \
        uint4* dh = (uint4*)(smem + SM_AHI + arow * ROWB + csub * 32);        \
        uint4* dl = (uint4*)(smem + SM_ALO + arow * ROWB + csub * 32);        \
        __nv_bfloat16 h0, h1, l0, l1;                                         \
        uint4 H, L;                                                           \
        split1(f0.x, h0, l0); split1(f0.y, h1, l1);                           \
        H.x = packbf(h0, h1); L.x = packbf(l0, l1);                           \
        split1(f0.z, h0, l0); split1(f0.w, h1, l1);                           \
        H.y = packbf(h0, h1); L.y = packbf(l0, l1);                           \
        split1(f1.x, h0, l0); split1(f1.y, h1, l1);                           \
        H.z = packbf(h0, h1); L.z = packbf(l0, l1);                           \
        split1(f1.z, h0, l0); split1(f1.w, h1, l1);                           \
        H.w = packbf(h0, h1); L.w = packbf(l0, l1);                           \
        dh[0] = H; dl[0] = L;                                                 \
        split1(f2.x, h0, l0); split1(f2.y, h1, l1);                           \
        H.x = packbf(h0, h1); L.x = packbf(l0, l1);                           \
        split1(f2.z, h0, l0); split1(f2.w, h1, l1);                           \
        H.y = packbf(h0, h1); L.y = packbf(l0, l1);                           \
        split1(f3.x, h0, l0); split1(f3.y, h1, l1);                           \
        H.z = packbf(h0, h1); L.z = packbf(l0, l1);                           \
        split1(f3.z, h0, l0); split1(f3.w, h1, l1);                           \
        H.w = packbf(h0, h1); L.w = packbf(l0, l1);                           \
        dh[1] = H; dl[1] = L;                                                 \
    }

    if (fullTile) {
        CONVERT_CHUNK(0, mbar_wait(mb0, 0);,
            if (tid == 0) {
                MBAR_EXPECT(mb0, 16384);
                BULK_G2S(sbase + SM_SCR,
                         (const char*)W + (size_t)(v0 + 64) * 512, 16384, mb0);
            })
        CONVERT_CHUNK(1, mbar_wait(mb1, 0);,
            if (tid == 0) {
                MBAR_EXPECT(mb1, 16384);
                BULK_G2S(sbase + SM_SCR + 16384,
                         (const char*)W + (size_t)(v0 + 96) * 512, 16384, mb1);
            })
        CONVERT_CHUNK(2, mbar_wait(mb0, 1);, )
        CONVERT_CHUNK(3, mbar_wait(mb1, 1);,
            if (tid == 0) {
                MBAR_EXPECT(mbU, 2 * BATCH * ROWB);
                BULK_G2S(sbase + SM_UHI, (const char*)g_upadh4,
                         BATCH * ROWB, mbU);
                BULK_G2S(sbase + SM_ULO, (const char*)g_upadl4,
                         BATCH * ROWB, mbU);
            })
    } else {
        CONVERT_CHUNK(0, CPWAIT(1);, ISSUE_CHUNK_SLOW(2))
        CONVERT_CHUNK(1, CPWAIT(1);, ISSUE_CHUNK_SLOW(3))
        CONVERT_CHUNK(2, CPWAIT(1);, )
        CONVERT_CHUNK(3, CPWAIT(0);,
            if (tid == 0) {
                MBAR_EXPECT(mbU, 2 * BATCH * ROWB);
                BULK_G2S(sbase + SM_UHI, (const char*)g_upadh4,
                         BATCH * ROWB, mbU);
                BULK_G2S(sbase + SM_ULO, (const char*)g_upadl4,
                         BATCH * ROWB, mbU);
            })
    }

    mbar_wait(mbU, 0);
    __syncthreads();        // A-tile writes from chunk 3 visible to all warps

    // ---- ldmatrix lane offsets ----
    int ar = lane & 15;
    int ac = (lane >> 4) * 8;
    int br = (lane & 7) + ((lane & 16) ? 8 : 0);
    int bc = ((lane >> 3) & 1) * 8;
    uint32_t aoff0 = (uint32_t)((32 * wm + ar) * ROWB + ac * 2);
    uint32_t aoff1 = aoff0 + 16 * ROWB;
    uint32_t boff0 = (uint32_t)((32 * wn + br) * ROWB + bc * 2);
    uint32_t boff1 = boff0 + 16 * ROWB;

    float acc[2][4][4];
#pragma unroll
    for (int mi = 0; mi < 2; ++mi)
#pragma unroll
        for (int j = 0; j < 4; ++j)
#pragma unroll
            for (int q = 0; q < 4; ++q) acc[mi][j][q] = 0.f;

#pragma unroll
    for (int ks = 0; ks < 8; ++ks) {
        uint32_t k2 = (uint32_t)(ks * 32);
        uint32_t AH[8], AL[8], BH[8], BL[8];
        ldsm_x4(AH[0], AH[1], AH[2], AH[3], sbase + SM_AHI + aoff0 + k2);
        ldsm_x4(AH[4], AH[5], AH[6], AH[7], sbase + SM_AHI + aoff1 + k2);
        ldsm_x4(AL[0], AL[1], AL[2], AL[3], sbase + SM_ALO + aoff0 + k2);
        ldsm_x4(AL[4], AL[5], AL[6], AL[7], sbase + SM_ALO + aoff1 + k2);
        ldsm_x4(BH[0], BH[1], BH[2], BH[3], sbase + SM_UHI + boff0 + k2);
        ldsm_x4(BH[4], BH[5], BH[6], BH[7], sbase + SM_UHI + boff1 + k2);
        ldsm_x4(BL[0], BL[1], BL[2], BL[3], sbase + SM_ULO + boff0 + k2);
        ldsm_x4(BL[4], BL[5], BL[6], BL[7], sbase + SM_ULO + boff1 + k2);
#pragma unroll
        for (int mi = 0; mi < 2; ++mi) {
#pragma unroll
            for (int j = 0; j < 4; ++j) {
                mma16816(acc[mi][j], &AH[4 * mi], &BH[2 * j]);   // hi*hi
                mma16816(acc[mi][j], &AH[4 * mi], &BL[2 * j]);   // hi*lo
                mma16816(acc[mi][j], &AL[4 * mi], &BH[2 * j]);   // lo*hi
            }
        }
    }

    // ---- epilogue: transpose via smem (stride 67), consecutive-v stores ----
    __syncthreads();
    {
        float* smemT = (float*)smem;          // 128 x 67 floats, reuses A region
        int mrow = lane >> 2;
        int ncol = (lane & 3) * 2;
#pragma unroll
        for (int mi = 0; mi < 2; ++mi) {
            int va = 32 * wm + 16 * mi + mrow;
            int vb = va + 8;
#pragma unroll
            for (int j = 0; j < 4; ++j) {
                int b0 = 32 * wn + 8 * j + ncol;
                smemT[va * 67 + b0]     = acc[mi][j][0];
                smemT[va * 67 + b0 + 1] = acc[mi][j][1];
                smemT[vb * 67 + b0]     = acc[mi][j][2];
                smemT[vb * 67 + b0 + 1] = acc[mi][j][3];
            }
        }
        __syncthreads();
        const float* bias_s = (const float*)(smem + SM_BIAS);
        for (int bb = w; bb < BATCH; bb += 8) {
            size_t rowbase = (size_t)bb * VOCAB;
#pragma unroll
            for (int vh = 0; vh < 4; ++vh) {
                int vl = vh * 32 + lane;
                int v = v0 + vl;
                if (v < VOCAB)
                    out[rowbase + v] = smemT[vl * 67 + bb] + bias_s[vl];
            }
        }
    }
}

// ---------------------------------------------------------------------------
extern "C" void kernel_launch(void* const* d_in, const int* in_sizes, int n_in,
                              void* d_out, int out_size) {
    const int*   stories   = (const int*)d_in[0];
    const int*   questions = (const int*)d_in[1];
    const int*   masks     = (const int*)d_in[2];
    const float* WA        = (const float*)d_in[3];
    const float* WB        = (const float*)d_in[4];
    const float* WC        = (const float*)d_in[5];
    const float* WAT       = (const float*)d_in[6];
    const float* WCT       = (const float*)d_in[7];
    const float* Wlin      = (const float*)d_in[8];
    const float* blin      = (const float*)d_in[9];
    float* out = (float*)d_out;

    cudaFuncSetAttribute(fused_kernel,
                         cudaFuncAttributeMaxDynamicSharedMemorySize, FS_TOTB);
    cudaFuncSetAttribute(linear_mma_kernel,
                         cudaFuncAttributeMaxDynamicSharedMemorySize, SM_TOT);

    fused_kernel<<<BATCH, 512, FS_TOTB>>>(stories, questions, masks,
                                          (const float4*)WA, (const float4*)WB,
                                          (const float4*)WC, (const float4*)WAT,
                                          (const float4*)WCT);
    linear_mma_kernel<<<NBLK, 256, SM_TOT>>>(Wlin, blin, out);
}